// round 15
// baseline (speedup 1.0000x reference)
#include <cuda_runtime.h>
#include <cuda_fp16.h>

#define NX 192
#define NY 192
#define NZ 192
#define NB 2
#define WIN 9
#define PAD 4
#define WS_INV (1.0f / 729.0f)
#define EPS 1e-5f

#define YC 48                   /* y-chunk per (blockIdx half, threadIdx.y) */
#define XCHUNKS 6
#define XC (NX / XCHUNKS)       /* 32 */
#define NZ2 (NZ / 2)            /* 96 float2/half2 per row */

constexpr size_t NTOT  = (size_t)NB * NX * NY * NZ;   // 14,155,776
constexpr size_t NTOT4 = NTOT / 4;                    // uint2 (4 halfs) per channel
constexpr int QUAD_PLANE = NY * NZ / 4;               // uint2 per x-slice = 9216

// Scratch: 5 channels {I_sum, J_sum, I2_sum, J2_sum, IJ_sum}, Z+Y filtered, fp16.
__device__ __half  g_buf[5 * NTOT];
__device__ double  g_accum;

// Persistent-state management: dedicated kernels + atomicAdd (proven R6-R13;
// both fused-zero/ticket (R4/R5) and partial-sum finalize (R14) variants failed).
__global__ void zero_accum_kernel() { g_accum = 0.0; }
__global__ void finalize_kernel(float* __restrict__ out) {
    out[0] = (float)(-g_accum / (double)NTOT);
}

__device__ __forceinline__ unsigned int pack_h2(float a, float b) {
    const __half2 h = __floats2half2_rn(a, b);
    return *reinterpret_cast<const unsigned int*>(&h);
}
__device__ __forceinline__ float2 unpack_h2(unsigned int w) {
    return __half22float2(*reinterpret_cast<const __half2*>(&w));
}

// ---------------------------------------------------------------------------
// pass12: fused Z-filter + Y-filter. Thread = float2 z-pair; threadIdx.y = y
// sub-chunk; grid 768 blocks. cp.async staging into a 3-row smem ring, one
// barrier per row. 8-slot q-ring (fp16 packed). Scratch stores use __stcs
// (no temporal reuse: 136MB > L2) to keep L2 for the I/J read stream.
// ---------------------------------------------------------------------------
__global__ __launch_bounds__(192, 6) void pass12(const float* __restrict__ I,
                                                 const float* __restrict__ J) {
    __shared__ float2 sIf[2][3][NZ2 + PAD];        // [chunk][buf][z]
    __shared__ float2 sJf[2][3][NZ2 + PAD];
    __shared__ uint4  ringA[2][8][NZ2];            // q0..q3 packed (A,B) half2
    __shared__ unsigned int ringB[2][8][NZ2];      // q4 packed

    const int c    = threadIdx.y;                  // sub-chunk 0/1
    const int tz   = threadIdx.x;                  // 0..95
    const int id   = blockIdx.x;                   // 0 .. NB*NX*2-1
    const int half = id & 1;
    const int bx   = id >> 1;                      // (b,x): 0..NB*NX-1
    const size_t planeBase = (size_t)bx * NY * NZ;
    const int y0 = (half * 2 + c) * YC;
    const int ylEnd = y0 + YC + PAD;

    if (tz < 2) {   // z halo: 2 float2 each side, all 3 buffers
#pragma unroll
        for (int rb = 0; rb < 3; ++rb) {
            sIf[c][rb][tz] = make_float2(0.f, 0.f);
            sJf[c][rb][tz] = make_float2(0.f, 0.f);
            sIf[c][rb][NZ2 + 2 + tz] = make_float2(0.f, 0.f);
            sJf[c][rb][NZ2 + 2 + tz] = make_float2(0.f, 0.f);
        }
    }

    const float2* __restrict__ I2 = reinterpret_cast<const float2*>(I + planeBase);
    const float2* __restrict__ J2 = reinterpret_cast<const float2*>(J + planeBase);
    __half2* __restrict__ h2buf = reinterpret_cast<__half2*>(g_buf);

    // Issue async copy of row into buffer rb; ALWAYS commits a group (empty
    // group for out-of-range rows keeps the wait_group count aligned).
    auto issue = [&](int row, int rb) {
        float2* dstI = &sIf[c][rb][tz + 2];
        float2* dstJ = &sJf[c][rb][tz + 2];
        if (row >= 0 && row < NY && row < ylEnd) {
            const unsigned int dI = (unsigned int)__cvta_generic_to_shared(dstI);
            const unsigned int dJ = (unsigned int)__cvta_generic_to_shared(dstJ);
            const float2* srcI = I2 + (size_t)row * NZ2 + tz;
            const float2* srcJ = J2 + (size_t)row * NZ2 + tz;
            asm volatile(
                "cp.async.ca.shared.global [%0], [%1], 8;\n\t"
                "cp.async.ca.shared.global [%2], [%3], 8;"
                :: "r"(dI), "l"(srcI), "r"(dJ), "l"(srcJ) : "memory");
        } else {
            *dstI = make_float2(0.f, 0.f);
            *dstJ = make_float2(0.f, 0.f);
        }
        asm volatile("cp.async.commit_group;" ::: "memory");
    };

    const int yl0 = y0 - PAD;
    issue(yl0,     0);
    issue(yl0 + 1, 1);

    float sA0 = 0.f, sA1 = 0.f, sA2 = 0.f, sA3 = 0.f, sA4 = 0.f;
    float sB0 = 0.f, sB1 = 0.f, sB2 = 0.f, sB3 = 0.f, sB4 = 0.f;
    int rb = 0;                            // buffer holding row yl

    for (int yl = yl0; yl < ylEnd; ++yl) {
        asm volatile("cp.async.wait_group 1;" ::: "memory");
        __syncthreads();                   // row yl visible; row yl-1 consumed

        // Window u[0..9] = raw z (2*tz-4 .. 2*tz+5), aligned float2 reads.
        float u[10], v[10];
#pragma unroll
        for (int j = 0; j < 5; ++j) {
            const float2 tu = sIf[c][rb][tz + j];
            const float2 tv = sJf[c][rb][tz + j];
            u[2 * j] = tu.x; u[2 * j + 1] = tu.y;
            v[2 * j] = tv.x; v[2 * j + 1] = tv.y;
        }

        // Issue row yl+2 into buffer (rb+2)%3 (held row yl-1; consumed).
        {
            int rb2 = rb + 2; if (rb2 >= 3) rb2 -= 3;
            issue(yl + 2, rb2);
        }

        // Shared middle (taps 1..8), then edge taps for the two outputs.
        float m0 = 0.f, m1 = 0.f, m2 = 0.f, m3 = 0.f, m4 = 0.f;
#pragma unroll
        for (int i = 1; i < 9; ++i) {
            m0 += u[i];             m1 += v[i];
            m2 = fmaf(u[i], u[i], m2);
            m3 = fmaf(v[i], v[i], m3);
            m4 = fmaf(u[i], v[i], m4);
        }
        const float qA0 = m0 + u[0],                 qB0 = m0 + u[9];
        const float qA1 = m1 + v[0],                 qB1 = m1 + v[9];
        const float qA2 = fmaf(u[0], u[0], m2),      qB2 = fmaf(u[9], u[9], m2);
        const float qA3 = fmaf(v[0], v[0], m3),      qB3 = fmaf(v[9], v[9], m3);
        const float qA4 = fmaf(u[0], v[0], m4),      qB4 = fmaf(u[9], v[9], m4);

        sA0 += qA0; sA1 += qA1; sA2 += qA2; sA3 += qA3; sA4 += qA4;
        sB0 += qB0; sB1 += qB1; sB2 += qB2; sB3 += qB3; sB4 += qB4;

        const int slot = yl & 7;           // 8-slot ring; AND safe for yl<0

        if (yl >= y0 + PAD) {
            const int yo = yl - PAD;
            const size_t o = planeBase / 2 + (size_t)yo * NZ2 + tz;
            __stcs(&h2buf[0 * (NTOT / 2) + o], __floats2half2_rn(sA0, sB0));
            __stcs(&h2buf[1 * (NTOT / 2) + o], __floats2half2_rn(sA1, sB1));
            __stcs(&h2buf[2 * (NTOT / 2) + o], __floats2half2_rn(sA2, sB2));
            __stcs(&h2buf[3 * (NTOT / 2) + o], __floats2half2_rn(sA3, sB3));
            __stcs(&h2buf[4 * (NTOT / 2) + o], __floats2half2_rn(sA4, sB4));
            // Row yl-8 lives in slot (yl-8)&7 == yl&7: read, then overwrite.
            const uint4 w = ringA[c][slot][tz];
            const unsigned int w4 = ringB[c][slot][tz];
            float2 f;
            f = unpack_h2(w.x); sA0 -= f.x; sB0 -= f.y;
            f = unpack_h2(w.y); sA1 -= f.x; sB1 -= f.y;
            f = unpack_h2(w.z); sA2 -= f.x; sB2 -= f.y;
            f = unpack_h2(w.w); sA3 -= f.x; sB3 -= f.y;
            f = unpack_h2(w4);  sA4 -= f.x; sB4 -= f.y;
        }

        {
            uint4 w;
            w.x = pack_h2(qA0, qB0);
            w.y = pack_h2(qA1, qB1);
            w.z = pack_h2(qA2, qB2);
            w.w = pack_h2(qA3, qB3);
            ringA[c][slot][tz] = w;
            ringB[c][slot][tz] = pack_h2(qA4, qB4);
        }

        rb = (rb == 2) ? 0 : rb + 1;
    }
}

// ---------------------------------------------------------------------------
// pass3: sliding 9-slice window along X, fused NCC + mean. Each thread owns
// 4 consecutive z-voxels (uint2 = 2 half2 per channel -> LDG.64, __ldcs
// streaming). Block sum -> atomicAdd(g_accum) (proven R13 form).
// ---------------------------------------------------------------------------
__global__ __launch_bounds__(256) void pass3_x_ncc() {
    const int x0 = blockIdx.y * XC;
    const int t  = blockIdx.x * blockDim.x + threadIdx.x;  // 0 .. NB*QUAD_PLANE-1
    const int b  = t / QUAD_PLANE;
    const int yz = t % QUAD_PLANE;

    const uint2* __restrict__ pk[5];
    {
        const uint2* base = reinterpret_cast<const uint2*>(g_buf) +
                            (size_t)b * NX * QUAD_PLANE + yz;
#pragma unroll
        for (int k = 0; k < 5; ++k) pk[k] = base + (size_t)k * NTOT4;
    }

    float s[5][4];
#pragma unroll
    for (int k = 0; k < 5; ++k)
#pragma unroll
        for (int l = 0; l < 4; ++l) s[k][l] = 0.f;

    auto slice_add = [&](int xs) {
        const size_t o = (size_t)xs * QUAD_PLANE;
#pragma unroll
        for (int k = 0; k < 5; ++k) {
            const uint2 w = __ldcs(&pk[k][o]);
            const float2 fl = unpack_h2(w.x);
            const float2 fh = unpack_h2(w.y);
            s[k][0] += fl.x; s[k][1] += fl.y; s[k][2] += fh.x; s[k][3] += fh.y;
        }
    };
    auto slice_sub = [&](int xs) {
        const size_t o = (size_t)xs * QUAD_PLANE;
#pragma unroll
        for (int k = 0; k < 5; ++k) {
            const uint2 w = __ldcs(&pk[k][o]);
            const float2 fl = unpack_h2(w.x);
            const float2 fh = unpack_h2(w.y);
            s[k][0] -= fl.x; s[k][1] -= fl.y; s[k][2] -= fh.x; s[k][3] -= fh.y;
        }
    };

    const int pre0 = (x0 - PAD > 0) ? (x0 - PAD) : 0;
#pragma unroll 4
    for (int x = pre0; x < x0 + PAD; ++x) slice_add(x);

    float acc = 0.f;
#pragma unroll 2
    for (int x = x0; x < x0 + XC; ++x) {
        const int xp = x + PAD;
        if (xp < NX) slice_add(xp);
#pragma unroll
        for (int l = 0; l < 4; ++l) {
            const float cross = s[4][l] - s[0][l] * s[1][l] * WS_INV;
            const float ivar  = s[2][l] - s[0][l] * s[0][l] * WS_INV;
            const float jvar  = s[3][l] - s[1][l] * s[1][l] * WS_INV;
            acc += (cross * cross) / (ivar * jvar + EPS);
        }
        const int xm = x - PAD;
        if (xm >= 0) slice_sub(xm);
    }

    __shared__ float red[256];
    red[threadIdx.x] = acc;
    __syncthreads();
#pragma unroll
    for (int o = 128; o > 0; o >>= 1) {
        if (threadIdx.x < o) red[threadIdx.x] += red[threadIdx.x + o];
        __syncthreads();
    }
    if (threadIdx.x == 0) atomicAdd(&g_accum, (double)red[0]);
}

extern "C" void kernel_launch(void* const* d_in, const int* in_sizes, int n_in,
                              void* d_out, int out_size) {
    const float* I = (const float*)d_in[0];
    const float* J = (const float*)d_in[1];
    float* out = (float*)d_out;

    zero_accum_kernel<<<1, 1>>>();
    pass12<<<NB * NX * 2, dim3(NZ2, 2)>>>(I, J);
    {
        dim3 grid((NB * QUAD_PLANE) / 256, XCHUNKS);
        pass3_x_ncc<<<grid, 256>>>();
    }
    finalize_kernel<<<1, 1>>>(out);
}

// round 16
// speedup vs baseline: 1.4167x; 1.4167x over previous
#include <cuda_runtime.h>
#include <cuda_fp16.h>

#define NX 192
#define NY 192
#define NZ 192
#define NB 2
#define WIN 9
#define PAD 4
#define WS_INV (1.0f / 729.0f)
#define EPS 1e-5f

#define YC 48                   /* y-chunk per (blockIdx half, threadIdx.y) */
#define XCHUNKS 6
#define XC (NX / XCHUNKS)       /* 32 */
#define NZ2 (NZ / 2)            /* 96 float2/half2 per row */

constexpr size_t NTOT  = (size_t)NB * NX * NY * NZ;   // 14,155,776
constexpr size_t NPAIR = NTOT / 2;                    // voxel-pairs total
constexpr int HALF_PLANE = NY * NZ / 2;               // voxel-pairs per x-slice

// Scratch, channel-interleaved per voxel-pair: ch0..3 in one uint4 (4x half2),
// ch4 in one uint. Same fp16 values as the old 5-plane layout.
__device__ uint4         g_buf4[NPAIR];
__device__ unsigned int  g_buf1[NPAIR];
__device__ double        g_accum;

// Persistent-state management: dedicated kernels + atomicAdd. PROVEN R6-R15.
// Both redesigns (ticket counter R4/R5, partial-sum finalize R14) failed.
__global__ void zero_accum_kernel() { g_accum = 0.0; }
__global__ void finalize_kernel(float* __restrict__ out) {
    out[0] = (float)(-g_accum / (double)NTOT);
}

__device__ __forceinline__ unsigned int pack_h2(float a, float b) {
    const __half2 h = __floats2half2_rn(a, b);
    return *reinterpret_cast<const unsigned int*>(&h);
}
__device__ __forceinline__ float2 unpack_h2(unsigned int w) {
    return __half22float2(*reinterpret_cast<const __half2*>(&w));
}

// ---------------------------------------------------------------------------
// pass12: fused Z-filter + Y-filter. Thread = float2 z-pair; threadIdx.y = y
// sub-chunk; grid 768 blocks. cp.async staging into a 3-row smem ring, one
// barrier per row. 8-slot q-ring (fp16 packed). Epilogue: ONE STG.128 + ONE
// STG.32 per row (channel-interleaved scratch). NO cache hints (R15: -39us).
// ---------------------------------------------------------------------------
__global__ __launch_bounds__(192, 6) void pass12(const float* __restrict__ I,
                                                 const float* __restrict__ J) {
    __shared__ float2 sIf[2][3][NZ2 + PAD];        // [chunk][buf][z]
    __shared__ float2 sJf[2][3][NZ2 + PAD];
    __shared__ uint4  ringA[2][8][NZ2];            // q0..q3 packed (A,B) half2
    __shared__ unsigned int ringB[2][8][NZ2];      // q4 packed

    const int c    = threadIdx.y;                  // sub-chunk 0/1
    const int tz   = threadIdx.x;                  // 0..95
    const int id   = blockIdx.x;                   // 0 .. NB*NX*2-1
    const int half = id & 1;
    const int bx   = id >> 1;                      // (b,x): 0..NB*NX-1
    const size_t planeBase = (size_t)bx * NY * NZ;
    const int y0 = (half * 2 + c) * YC;
    const int ylEnd = y0 + YC + PAD;

    if (tz < 2) {   // z halo: 2 float2 each side, all 3 buffers
#pragma unroll
        for (int rb = 0; rb < 3; ++rb) {
            sIf[c][rb][tz] = make_float2(0.f, 0.f);
            sJf[c][rb][tz] = make_float2(0.f, 0.f);
            sIf[c][rb][NZ2 + 2 + tz] = make_float2(0.f, 0.f);
            sJf[c][rb][NZ2 + 2 + tz] = make_float2(0.f, 0.f);
        }
    }

    const float2* __restrict__ I2 = reinterpret_cast<const float2*>(I + planeBase);
    const float2* __restrict__ J2 = reinterpret_cast<const float2*>(J + planeBase);

    // Issue async copy of row into buffer rb; ALWAYS commits a group (empty
    // group for out-of-range rows keeps the wait_group count aligned).
    auto issue = [&](int row, int rb) {
        float2* dstI = &sIf[c][rb][tz + 2];
        float2* dstJ = &sJf[c][rb][tz + 2];
        if (row >= 0 && row < NY && row < ylEnd) {
            const unsigned int dI = (unsigned int)__cvta_generic_to_shared(dstI);
            const unsigned int dJ = (unsigned int)__cvta_generic_to_shared(dstJ);
            const float2* srcI = I2 + (size_t)row * NZ2 + tz;
            const float2* srcJ = J2 + (size_t)row * NZ2 + tz;
            asm volatile(
                "cp.async.ca.shared.global [%0], [%1], 8;\n\t"
                "cp.async.ca.shared.global [%2], [%3], 8;"
                :: "r"(dI), "l"(srcI), "r"(dJ), "l"(srcJ) : "memory");
        } else {
            *dstI = make_float2(0.f, 0.f);
            *dstJ = make_float2(0.f, 0.f);
        }
        asm volatile("cp.async.commit_group;" ::: "memory");
    };

    const int yl0 = y0 - PAD;
    issue(yl0,     0);
    issue(yl0 + 1, 1);

    float sA0 = 0.f, sA1 = 0.f, sA2 = 0.f, sA3 = 0.f, sA4 = 0.f;
    float sB0 = 0.f, sB1 = 0.f, sB2 = 0.f, sB3 = 0.f, sB4 = 0.f;
    int rb = 0;                            // buffer holding row yl

    for (int yl = yl0; yl < ylEnd; ++yl) {
        asm volatile("cp.async.wait_group 1;" ::: "memory");
        __syncthreads();                   // row yl visible; row yl-1 consumed

        // Window u[0..9] = raw z (2*tz-4 .. 2*tz+5), aligned float2 reads.
        float u[10], v[10];
#pragma unroll
        for (int j = 0; j < 5; ++j) {
            const float2 tu = sIf[c][rb][tz + j];
            const float2 tv = sJf[c][rb][tz + j];
            u[2 * j] = tu.x; u[2 * j + 1] = tu.y;
            v[2 * j] = tv.x; v[2 * j + 1] = tv.y;
        }

        // Issue row yl+2 into buffer (rb+2)%3 (held row yl-1; consumed).
        {
            int rb2 = rb + 2; if (rb2 >= 3) rb2 -= 3;
            issue(yl + 2, rb2);
        }

        // Shared middle (taps 1..8), then edge taps for the two outputs.
        float m0 = 0.f, m1 = 0.f, m2 = 0.f, m3 = 0.f, m4 = 0.f;
#pragma unroll
        for (int i = 1; i < 9; ++i) {
            m0 += u[i];             m1 += v[i];
            m2 = fmaf(u[i], u[i], m2);
            m3 = fmaf(v[i], v[i], m3);
            m4 = fmaf(u[i], v[i], m4);
        }
        const float qA0 = m0 + u[0],                 qB0 = m0 + u[9];
        const float qA1 = m1 + v[0],                 qB1 = m1 + v[9];
        const float qA2 = fmaf(u[0], u[0], m2),      qB2 = fmaf(u[9], u[9], m2);
        const float qA3 = fmaf(v[0], v[0], m3),      qB3 = fmaf(v[9], v[9], m3);
        const float qA4 = fmaf(u[0], v[0], m4),      qB4 = fmaf(u[9], v[9], m4);

        sA0 += qA0; sA1 += qA1; sA2 += qA2; sA3 += qA3; sA4 += qA4;
        sB0 += qB0; sB1 += qB1; sB2 += qB2; sB3 += qB3; sB4 += qB4;

        const int slot = yl & 7;           // 8-slot ring; AND safe for yl<0

        if (yl >= y0 + PAD) {
            const int yo = yl - PAD;
            const size_t o = planeBase / 2 + (size_t)yo * NZ2 + tz;
            uint4 wq;
            wq.x = pack_h2(sA0, sB0);
            wq.y = pack_h2(sA1, sB1);
            wq.z = pack_h2(sA2, sB2);
            wq.w = pack_h2(sA3, sB3);
            g_buf4[o] = wq;                         // one STG.128
            g_buf1[o] = pack_h2(sA4, sB4);          // one STG.32
            // Row yl-8 lives in slot (yl-8)&7 == yl&7: read, then overwrite.
            const uint4 w = ringA[c][slot][tz];
            const unsigned int w4 = ringB[c][slot][tz];
            float2 f;
            f = unpack_h2(w.x); sA0 -= f.x; sB0 -= f.y;
            f = unpack_h2(w.y); sA1 -= f.x; sB1 -= f.y;
            f = unpack_h2(w.z); sA2 -= f.x; sB2 -= f.y;
            f = unpack_h2(w.w); sA3 -= f.x; sB3 -= f.y;
            f = unpack_h2(w4);  sA4 -= f.x; sB4 -= f.y;
        }

        {
            uint4 w;
            w.x = pack_h2(qA0, qB0);
            w.y = pack_h2(qA1, qB1);
            w.z = pack_h2(qA2, qB2);
            w.w = pack_h2(qA3, qB3);
            ringA[c][slot][tz] = w;
            ringB[c][slot][tz] = pack_h2(qA4, qB4);
        }

        rb = (rb == 2) ? 0 : rb + 1;
    }
}

// ---------------------------------------------------------------------------
// pass3: sliding 9-slice window along X, fused NCC + mean. Thread = one
// voxel-pair: per slice one LDG.128 (ch0..3) + one LDG.32 (ch4). Grid 864
// blocks. Block sum -> atomicAdd(g_accum) (proven form). No cache hints.
// ---------------------------------------------------------------------------
__global__ __launch_bounds__(256) void pass3_x_ncc() {
    const int x0 = blockIdx.y * XC;
    const int t  = blockIdx.x * blockDim.x + threadIdx.x;  // 0 .. NB*HALF_PLANE-1
    const int b  = t / HALF_PLANE;
    const int yz = t % HALF_PLANE;

    const uint4* __restrict__ p4 =
        g_buf4 + (size_t)b * NX * HALF_PLANE + yz;
    const unsigned int* __restrict__ p1 =
        g_buf1 + (size_t)b * NX * HALF_PLANE + yz;

    float s[5][2];
#pragma unroll
    for (int k = 0; k < 5; ++k) { s[k][0] = 0.f; s[k][1] = 0.f; }

    auto slice_add = [&](int xs) {
        const size_t o = (size_t)xs * HALF_PLANE;
        const uint4 w = p4[o];
        const unsigned int e = p1[o];
        float2 f;
        f = unpack_h2(w.x); s[0][0] += f.x; s[0][1] += f.y;
        f = unpack_h2(w.y); s[1][0] += f.x; s[1][1] += f.y;
        f = unpack_h2(w.z); s[2][0] += f.x; s[2][1] += f.y;
        f = unpack_h2(w.w); s[3][0] += f.x; s[3][1] += f.y;
        f = unpack_h2(e);   s[4][0] += f.x; s[4][1] += f.y;
    };
    auto slice_sub = [&](int xs) {
        const size_t o = (size_t)xs * HALF_PLANE;
        const uint4 w = p4[o];
        const unsigned int e = p1[o];
        float2 f;
        f = unpack_h2(w.x); s[0][0] -= f.x; s[0][1] -= f.y;
        f = unpack_h2(w.y); s[1][0] -= f.x; s[1][1] -= f.y;
        f = unpack_h2(w.z); s[2][0] -= f.x; s[2][1] -= f.y;
        f = unpack_h2(w.w); s[3][0] -= f.x; s[3][1] -= f.y;
        f = unpack_h2(e);   s[4][0] -= f.x; s[4][1] -= f.y;
    };

    const int pre0 = (x0 - PAD > 0) ? (x0 - PAD) : 0;
#pragma unroll 4
    for (int x = pre0; x < x0 + PAD; ++x) slice_add(x);

    float acc = 0.f;
#pragma unroll 2
    for (int x = x0; x < x0 + XC; ++x) {
        const int xp = x + PAD;
        if (xp < NX) slice_add(xp);
#pragma unroll
        for (int l = 0; l < 2; ++l) {
            const float cross = s[4][l] - s[0][l] * s[1][l] * WS_INV;
            const float ivar  = s[2][l] - s[0][l] * s[0][l] * WS_INV;
            const float jvar  = s[3][l] - s[1][l] * s[1][l] * WS_INV;
            acc += (cross * cross) / (ivar * jvar + EPS);
        }
        const int xm = x - PAD;
        if (xm >= 0) slice_sub(xm);
    }

    __shared__ float red[256];
    red[threadIdx.x] = acc;
    __syncthreads();
#pragma unroll
    for (int o = 128; o > 0; o >>= 1) {
        if (threadIdx.x < o) red[threadIdx.x] += red[threadIdx.x + o];
        __syncthreads();
    }
    if (threadIdx.x == 0) atomicAdd(&g_accum, (double)red[0]);
}

extern "C" void kernel_launch(void* const* d_in, const int* in_sizes, int n_in,
                              void* d_out, int out_size) {
    const float* I = (const float*)d_in[0];
    const float* J = (const float*)d_in[1];
    float* out = (float*)d_out;

    zero_accum_kernel<<<1, 1>>>();
    pass12<<<NB * NX * 2, dim3(NZ2, 2)>>>(I, J);
    {
        dim3 grid((NB * HALF_PLANE) / 256, XCHUNKS);
        pass3_x_ncc<<<grid, 256>>>();
    }
    finalize_kernel<<<1, 1>>>(out);
}